// round 3
// baseline (speedup 1.0000x reference)
#include <cuda_runtime.h>

// DistanceTransformMap: exact 2-pass EDT + sqrt.
// Expanding-window search, ONE search per thread, chunk-of-4 candidate eval,
// LARGE-padded shared lines (no bounds branches in the hot loop).
//
// Exactness: all field values g >= 0 and <= LARGE, so:
//  - once d^2 >= best, no candidate at distance >= d can win (g >= 0);
//  - pad candidates LARGE + d^2 > LARGE >= best0 never win;
//  - extra candidates inside a chunk are valid upper bounds.
// All intermediates are exact integers < 2^24 in fp32 -> bit-exact vs reference.

constexpr int Bn = 4;
constexpr int Hn = 384;
constexpr int Wn = 384;
constexpr float LARGE = 2.0f * (float)(Hn * Hn + Wn * Wn);  // 589824 > 383^2

constexpr int PAD = 388;           // covers chunk overrun: d <= Wn+2 -> i+-d in [-386, 769]
constexpr int LW  = Wn + 2 * PAD;  // 1160 floats per padded line
constexpr int NT  = 768;           // threads per block = searches per block

__device__ float g_mid[Bn * Hn * Wn];  // natural layout [b][y][x]

// Expanding search on a padded line. p points at element i (pad applied).
__device__ __forceinline__ float edt_search(const float* __restrict__ p) {
    float best = p[0];
    float df = 1.0f;
    int d = 1;
    while (df * df < best && d < Wn) {
        const float v0 = p[d],     v1 = p[-d];
        const float v2 = p[d + 1], v3 = p[-(d + 1)];
        const float v4 = p[d + 2], v5 = p[-(d + 2)];
        const float v6 = p[d + 3], v7 = p[-(d + 3)];
        const float e0 = df, e1 = df + 1.0f, e2 = df + 2.0f, e3 = df + 3.0f;
        float c0 = fminf(fmaf(e0, e0, v0), fmaf(e0, e0, v1));
        float c1 = fminf(fmaf(e1, e1, v2), fmaf(e1, e1, v3));
        float c2 = fminf(fmaf(e2, e2, v4), fmaf(e2, e2, v5));
        float c3 = fminf(fmaf(e3, e3, v6), fmaf(e3, e3, v7));
        best = fminf(best, fminf(fminf(c0, c1), fminf(c2, c3)));
        df += 4.0f;
        d += 4;
    }
    return best;
}

// Fill left+right LARGE pads of both lines (disjoint from center writes).
__device__ __forceinline__ void fill_pads(float* __restrict__ sh, int t) {
    for (int k = t; k < 2 * 2 * PAD; k += NT) {
        const int ln = k / (2 * PAD);
        const int off = k - ln * 2 * PAD;
        const int idx = (off < PAD) ? off : (LW - 2 * PAD + off);
        sh[ln * LW + idx] = LARGE;
    }
}

// Pass 1: row EDT. 2 rows per block, one search per thread.
__global__ __launch_bounds__(NT) void edt_pass1(const float* __restrict__ mask) {
    __shared__ float sh[2 * LW];
    const int t = threadIdx.x;
    const size_t base = (size_t)blockIdx.x * 2 * Wn;   // 2 contiguous rows

    const float m = mask[base + t];                    // fully coalesced
    const int l = (t >= Wn) ? 1 : 0;
    const int i = t - l * Wn;
    sh[l * LW + PAD + i] = (m > 0.5f) ? LARGE : 0.0f;
    fill_pads(sh, t);
    __syncthreads();

    const float best = edt_search(&sh[l * LW + PAD + i]);
    g_mid[base + t] = best;                            // fully coalesced
}

// Pass 2: column EDT on 2-column strips, one search per thread.
__global__ __launch_bounds__(NT) void edt_pass2(float* __restrict__ out) {
    __shared__ float sh[2 * LW];
    const int t = threadIdx.x;
    const int blk = blockIdx.x;
    const int b = blk / (Wn / 2);
    const int x0 = (blk - b * (Wn / 2)) * 2;

    const float* __restrict__ src = g_mid + (size_t)b * Hn * Wn + x0;
    if (t < Hn) {
        const float2 v = *reinterpret_cast<const float2*>(src + (size_t)t * Wn);
        sh[PAD + t] = v.x;
        sh[LW + PAD + t] = v.y;
    }
    fill_pads(sh, t);
    __syncthreads();

    const int l = (t >= Hn) ? 1 : 0;
    const int y = t - l * Hn;
    const float r = sqrtf(edt_search(&sh[l * LW + PAD + y]));

    __syncthreads();                 // all searches done reading sh
    sh[l * Hn + y] = r;              // compact stage for paired stores
    __syncthreads();

    const int yy = t >> 1, c = t & 1;
    out[((size_t)b * Hn + yy) * Wn + x0 + c] = sh[c * Hn + yy];
}

extern "C" void kernel_launch(void* const* d_in, const int* in_sizes, int n_in,
                              void* d_out, int out_size) {
    const float* mask = (const float*)d_in[0];
    float* out = (float*)d_out;
    (void)in_sizes; (void)n_in; (void)out_size;

    edt_pass1<<<Bn * Hn / 2, NT>>>(mask);
    edt_pass2<<<Bn * (Wn / 2), NT>>>(out);
}